// round 9
// baseline (speedup 1.0000x reference)
#include <cuda_runtime.h>
#include <cstdint>

// C4TransformerVM: exact 4-byte ripple-carry add over one-hot byte encodings.
// Decode (argmax) -> uint32 add (final carry discarded) -> one-hot encode.
//
// History:
//  R3 fused 67.6us @ DRAM 69% (regs=40, MLP~6).
//  R4 split: regression; encode (pure STG.128 stream) capped at ~2.0 TB/s.
//  R5 launch_bounds(256,3): 63.8us @ 77.6% (MLP=16).
//  R6 zero-store overlap: 63.5us @ 79.2%.
//  R7 persistent grid: regression (serialized tiles per warp).
//  R8 64-thread CTAs: neutral (56.6us kernel).
//  R9 theory: kernel is STG.128 ISSUE bound (12 cyc/warp-store -> ~2.3 TB/s
//     store ceiling; fused kernel writes 128MB/56.6us = 2.26 TB/s = ceiling).
//     Fix: write output through SMEM + cp.async.bulk (TMA/UBLKCP path),
//     4 bulk stores of 8KB per CTA instead of 256 STG.128.

__device__ __forceinline__ uint32_t scan8_mask(float4 v0, float4 v1, int base, int sh) {
    uint32_t idx = 0;
    if (v0.x > 0.5f) idx = (uint32_t)(base + 0);
    if (v0.y > 0.5f) idx = (uint32_t)(base + 1);
    if (v0.z > 0.5f) idx = (uint32_t)(base + 2);
    if (v0.w > 0.5f) idx = (uint32_t)(base + 3);
    if (v1.x > 0.5f) idx = (uint32_t)(base + 4);
    if (v1.y > 0.5f) idx = (uint32_t)(base + 5);
    if (v1.z > 0.5f) idx = (uint32_t)(base + 6);
    if (v1.w > 0.5f) idx = (uint32_t)(base + 7);
    return idx << sh;
}

__device__ __forceinline__ uint32_t smem_u32(const void* p) {
    uint32_t a;
    asm("{ .reg .u64 t; cvta.to.shared.u64 t, %1; cvt.u32.u64 %0, t; }"
        : "=r"(a) : "l"(p));
    return a;
}

__global__ __launch_bounds__(256, 3) void neural_alu_add_kernel(
    const float* __restrict__ a,
    const float* __restrict__ b,
    float* __restrict__ out,
    int N)
{
    // Output staging tile: 4 byte-streams x 8 consecutive n x 256 floats = 32KB.
    __shared__ float buf[4][8][256];

    const int tid = threadIdx.x;
    const int wid = tid >> 5;           // warp -> local n
    const int lane = tid & 31;
    const int n0 = blockIdx.x * 8;
    const size_t n = (size_t)(n0 + wid);
    const int base = lane * 8;

    // ---- Phase 1: issue all 16 float4 loads (MLP = 16).
    float4 va[8], vb[8];
#pragma unroll
    for (int i = 0; i < 4; i++) {
        const float4* ra = reinterpret_cast<const float4*>(a + ((size_t)i * N + n) * 256);
        const float4* rb = reinterpret_cast<const float4*>(b + ((size_t)i * N + n) * 256);
        va[2 * i]     = __ldcs(ra + lane * 2);
        va[2 * i + 1] = __ldcs(ra + lane * 2 + 1);
        vb[2 * i]     = __ldcs(rb + lane * 2);
        vb[2 * i + 1] = __ldcs(rb + lane * 2 + 1);
    }

    // ---- Phase 2: zero this warp's 4 SMEM rows (STS.128, smem crossbar --
    // independent of the in-flight loads).
    const float4 z = make_float4(0.f, 0.f, 0.f, 0.f);
#pragma unroll
    for (int i = 0; i < 4; i++) {
        float4* p = reinterpret_cast<float4*>(&buf[i][wid][0]);
        p[lane * 2]     = z;
        p[lane * 2 + 1] = z;
    }

    // ---- Phase 3: decode. Pack byte-i index into bits [8i,8i+8); at most
    // one lane nonzero per byte (hot index 0 => all-zero, also correct).
    uint32_t Ap = 0, Bp = 0;
#pragma unroll
    for (int i = 0; i < 4; i++) {
        Ap |= scan8_mask(va[2 * i], va[2 * i + 1], base, 8 * i);
        Bp |= scan8_mask(vb[2 * i], vb[2 * i + 1], base, 8 * i);
    }
    const uint32_t A = __reduce_or_sync(0xffffffffu, Ap);
    const uint32_t B = __reduce_or_sync(0xffffffffu, Bp);
    const uint32_t S = A + B;           // carry out of byte 3 discarded

    // ---- Phase 4: owning lane patches the hot element in SMEM.
#pragma unroll
    for (int i = 0; i < 4; i++) {
        const int r = (int)((S >> (8 * i)) & 255u);
        if ((r >> 3) == lane) buf[i][wid][r] = 1.0f;
    }

    __syncthreads();

    // ---- Phase 5: 4 bulk-async stores of 8KB each (rows for stream i over
    // 8 consecutive n are contiguous in gmem). Replaces 256 STG.128 per CTA.
    if (tid < 4) {
        asm volatile("fence.proxy.async.shared::cta;" ::: "memory");
        const uint64_t gdst = (uint64_t)(out + ((size_t)tid * N + n0) * 256);
        const uint32_t ssrc = smem_u32(&buf[tid][0][0]);
        asm volatile(
            "cp.async.bulk.global.shared::cta.bulk_group [%0], [%1], %2;"
            :: "l"(gdst), "r"(ssrc), "n"(8 * 1024) : "memory");
        asm volatile("cp.async.bulk.commit_group;" ::: "memory");
        asm volatile("cp.async.bulk.wait_group 0;" ::: "memory");
    }
}

extern "C" void kernel_launch(void* const* d_in, const int* in_sizes, int n_in,
                              void* d_out, int out_size) {
    const float* a = (const float*)d_in[0];   // [4, N, 256] one-hot
    const float* b = (const float*)d_in[1];   // [4, N, 256] one-hot
    float* out = (float*)d_out;               // [4, N, 256]
    const int N = in_sizes[0] / (4 * 256);

    const int threads = 256;                  // 8 warps/block, warp = one n
    const int blocks = N / 8;                 // N = 32768 -> 4096 CTAs
    neural_alu_add_kernel<<<blocks, threads>>>(a, b, out, N);
}

// round 10
// speedup vs baseline: 1.0044x; 1.0044x over previous
#include <cuda_runtime.h>
#include <cstdint>

// C4TransformerVM: exact 4-byte ripple-carry add over one-hot byte encodings.
// softmax(temp=100) over integer logit gaps makes every intermediate one-hot
// to ~3.6e-44 in fp32 -> decode (argmax), uint32 add (final carry discarded),
// re-encode one-hot. Irreducible traffic: 256 MB read + 128 MB write.
//
// History:
//  R3 fused, regs=40, occ 61%: 67.6us @ DRAM 69%.
//  R4 split kernels: regression.
//  R5 launch_bounds(256,3) regs=80, occ 30%: 63.8us @ 77.6%.
//  R6 + zero-store overlap / owner-lane patch: 63.5us @ 79.2% (HBM 6474).
//  R7 persistent grid: regression (serialized tiles per warp).
//  R8 64-thread CTAs: neutral.
//  R9 TMA bulk stores: neutral -> STG-issue theory falsified. Plateau at
//     ~55.6us kernel / ~78% DRAM across 4 structural variants.
//  R10: probe the interior of the occ/MLP trade: launch_bounds(256,4)
//       -> 64 regs, ~12 loads in flight (still >> latency need), 32 warps/SM
//       (+33% issue slots to cover REDUX dead windows).

__device__ __forceinline__ uint32_t scan8_mask(float4 v0, float4 v1, int base, int sh) {
    uint32_t idx = 0;
    if (v0.x > 0.5f) idx = (uint32_t)(base + 0);
    if (v0.y > 0.5f) idx = (uint32_t)(base + 1);
    if (v0.z > 0.5f) idx = (uint32_t)(base + 2);
    if (v0.w > 0.5f) idx = (uint32_t)(base + 3);
    if (v1.x > 0.5f) idx = (uint32_t)(base + 4);
    if (v1.y > 0.5f) idx = (uint32_t)(base + 5);
    if (v1.z > 0.5f) idx = (uint32_t)(base + 6);
    if (v1.w > 0.5f) idx = (uint32_t)(base + 7);
    return idx << sh;
}

__global__ __launch_bounds__(256, 4) void neural_alu_add_kernel(
    const float* __restrict__ a,
    const float* __restrict__ b,
    float* __restrict__ out,
    int N)
{
    const int warp_id = (blockIdx.x * blockDim.x + threadIdx.x) >> 5;
    const int lane = threadIdx.x & 31;
    if (warp_id >= N) return;
    const size_t n = (size_t)warp_id;
    const int base = lane * 8;

    // ---- Phase 1: issue the float4 loads (compiler fits ~12 in flight
    // under the 64-reg budget; outstanding bytes still cover DRAM latency).
    float4 va[8], vb[8];
#pragma unroll
    for (int i = 0; i < 4; i++) {
        const float4* ra = reinterpret_cast<const float4*>(a + ((size_t)i * N + n) * 256);
        const float4* rb = reinterpret_cast<const float4*>(b + ((size_t)i * N + n) * 256);
        va[2 * i]     = __ldcs(ra + lane * 2);
        va[2 * i + 1] = __ldcs(ra + lane * 2 + 1);
        vb[2 * i]     = __ldcs(rb + lane * 2);
        vb[2 * i + 1] = __ldcs(rb + lane * 2 + 1);
    }

    // ---- Phase 2: store zeros to all 4 output rows (independent of the
    // loads; drains while reads are in flight).
    const float4 z = make_float4(0.f, 0.f, 0.f, 0.f);
#pragma unroll
    for (int i = 0; i < 4; i++) {
        float4* ro = reinterpret_cast<float4*>(out + ((size_t)i * N + n) * 256);
        __stcs(ro + lane * 2,     z);
        __stcs(ro + lane * 2 + 1, z);
    }

    // ---- Phase 3: decode. Pack byte-i index into bits [8i,8i+8); at most
    // one lane nonzero per byte (hot index 0 => all-zero, also correct), so
    // one OR-reduction per operand reconstructs the 32-bit word.
    uint32_t Ap = 0, Bp = 0;
#pragma unroll
    for (int i = 0; i < 4; i++) {
        Ap |= scan8_mask(va[2 * i], va[2 * i + 1], base, 8 * i);
        Bp |= scan8_mask(vb[2 * i], vb[2 * i + 1], base, 8 * i);
    }
    const uint32_t A = __reduce_or_sync(0xffffffffu, Ap);
    const uint32_t B = __reduce_or_sync(0xffffffffu, Bp);

    const uint32_t S = A + B;   // carry out of byte 3 discarded

    // ---- Phase 4: owning lane patches the hot element of each row. Same
    // thread + same address as its zero store -> program order guarantees
    // the 1.0 lands last.
#pragma unroll
    for (int i = 0; i < 4; i++) {
        const int r = (int)((S >> (8 * i)) & 255u);
        if ((r >> 3) == lane) {
            __stcs(out + ((size_t)i * N + n) * 256 + r, 1.0f);
        }
    }
}

extern "C" void kernel_launch(void* const* d_in, const int* in_sizes, int n_in,
                              void* d_out, int out_size) {
    const float* a = (const float*)d_in[0];   // [4, N, 256] one-hot
    const float* b = (const float*)d_in[1];   // [4, N, 256] one-hot
    float* out = (float*)d_out;               // [4, N, 256]
    const int N = in_sizes[0] / (4 * 256);

    const int threads = 256;                  // 8 warps/block, 1 warp per n
    const int blocks = (N * 32 + threads - 1) / threads;
    neural_alu_add_kernel<<<blocks, threads>>>(a, b, out, N);
}

// round 11
// speedup vs baseline: 1.0317x; 1.0272x over previous
#include <cuda_runtime.h>
#include <cstdint>

// C4TransformerVM: exact 4-byte ripple-carry add over one-hot byte encodings.
// softmax(temp=100) over integer logit gaps makes every intermediate one-hot
// to ~3.6e-44 in fp32 -> decode (argmax), uint32 add (final carry discarded),
// re-encode one-hot. Irreducible traffic: 256 MB read + 128 MB write.
//
// History:
//  R3 fused regs=40: 67.6us @ 69% DRAM.       R4 split: regression.
//  R5 lb(256,3) regs=80: 63.8us @ 77.6%.      R6 +zero-store overlap: 63.5us
//     @ 79.2% (HBM 6474 GB/s) <- best.        R7 persistent: regression.
//  R8 64-thr CTAs: neutral.  R9 TMA stores: neutral.  R10 occ 41%: neutral-.
//  Plateau: ~6.3-6.5 TB/s mixed-stream across 5 structural variants.
//  R11: Blackwell 256-bit memory ops (ld/st.global.v8.f32) — halves L1tex
//       wavefronts and LDG/STG instruction count; last untested lever.

__device__ __forceinline__ void ldg256(const float* p, float4& lo, float4& hi) {
    asm volatile(
        "ld.global.nc.v8.f32 {%0,%1,%2,%3,%4,%5,%6,%7}, [%8];"
        : "=f"(lo.x), "=f"(lo.y), "=f"(lo.z), "=f"(lo.w),
          "=f"(hi.x), "=f"(hi.y), "=f"(hi.z), "=f"(hi.w)
        : "l"(p));
}

__device__ __forceinline__ void stg256_zero(float* p) {
    asm volatile(
        "st.global.v8.f32 [%0], {%1,%1,%1,%1,%1,%1,%1,%1};"
        :: "l"(p), "f"(0.0f) : "memory");
}

__device__ __forceinline__ uint32_t scan8_mask(float4 v0, float4 v1, int base, int sh) {
    uint32_t idx = 0;
    if (v0.x > 0.5f) idx = (uint32_t)(base + 0);
    if (v0.y > 0.5f) idx = (uint32_t)(base + 1);
    if (v0.z > 0.5f) idx = (uint32_t)(base + 2);
    if (v0.w > 0.5f) idx = (uint32_t)(base + 3);
    if (v1.x > 0.5f) idx = (uint32_t)(base + 4);
    if (v1.y > 0.5f) idx = (uint32_t)(base + 5);
    if (v1.z > 0.5f) idx = (uint32_t)(base + 6);
    if (v1.w > 0.5f) idx = (uint32_t)(base + 7);
    return idx << sh;
}

__global__ __launch_bounds__(256, 3) void neural_alu_add_kernel(
    const float* __restrict__ a,
    const float* __restrict__ b,
    float* __restrict__ out,
    int N)
{
    const int warp_id = (blockIdx.x * blockDim.x + threadIdx.x) >> 5;
    const int lane = threadIdx.x & 31;
    if (warp_id >= N) return;
    const size_t n = (size_t)warp_id;
    const int base = lane * 8;

    // ---- Phase 1: 8x 256-bit loads (each lane: 8 contiguous floats/row).
    // One warp-instruction per 1KB row-half pair -> MLP=8 x 1KB in flight.
    float4 va[8], vb[8];
#pragma unroll
    for (int i = 0; i < 4; i++) {
        const float* ra = a + ((size_t)i * N + n) * 256 + base;
        const float* rb = b + ((size_t)i * N + n) * 256 + base;
        ldg256(ra, va[2 * i], va[2 * i + 1]);
        ldg256(rb, vb[2 * i], vb[2 * i + 1]);
    }

    // ---- Phase 2: zero all 4 output rows with 256-bit stores (independent
    // of the loads; drains while reads are in flight).
#pragma unroll
    for (int i = 0; i < 4; i++) {
        stg256_zero(out + ((size_t)i * N + n) * 256 + base);
    }

    // ---- Phase 3: decode. Pack byte-i index into bits [8i,8i+8); at most
    // one lane nonzero per byte (hot index 0 => all-zero, also correct), so
    // one OR-reduction per operand reconstructs the 32-bit word.
    uint32_t Ap = 0, Bp = 0;
#pragma unroll
    for (int i = 0; i < 4; i++) {
        Ap |= scan8_mask(va[2 * i], va[2 * i + 1], base, 8 * i);
        Bp |= scan8_mask(vb[2 * i], vb[2 * i + 1], base, 8 * i);
    }
    const uint32_t A = __reduce_or_sync(0xffffffffu, Ap);
    const uint32_t B = __reduce_or_sync(0xffffffffu, Bp);

    const uint32_t S = A + B;   // carry out of byte 3 discarded

    // ---- Phase 4: owning lane patches the hot element of each row. Same
    // thread + same address range as its zero store -> program order
    // guarantees the 1.0 lands last.
#pragma unroll
    for (int i = 0; i < 4; i++) {
        const int r = (int)((S >> (8 * i)) & 255u);
        if ((r >> 3) == lane) {
            out[((size_t)i * N + n) * 256 + r] = 1.0f;
        }
    }
}

extern "C" void kernel_launch(void* const* d_in, const int* in_sizes, int n_in,
                              void* d_out, int out_size) {
    const float* a = (const float*)d_in[0];   // [4, N, 256] one-hot
    const float* b = (const float*)d_in[1];   // [4, N, 256] one-hot
    float* out = (float*)d_out;               // [4, N, 256]
    const int N = in_sizes[0] / (4 * 256);

    const int threads = 256;                  // 8 warps/block, 1 warp per n
    const int blocks = (N * 32 + threads - 1) / threads;
    neural_alu_add_kernel<<<blocks, threads>>>(a, b, out, N);
}